// round 1
// baseline (speedup 1.0000x reference)
#include <cuda_runtime.h>
#include <cuda_bf16.h>
#include <math.h>

// Problem constants
#define Bn   32
#define Ln   4096
#define Hn   256
#define N2n  32
#define NLn  4
#define DOUTn 8

// ---------------- scratch (device globals; no allocation allowed) ----------------
__device__ float g_h[(size_t)Bn * Hn * Ln];       // 128 MB  current hidden (B,H,L)
__device__ float g_y[(size_t)Bn * Hn * Ln];       // 128 MB  gelu(ssm) output (B,H,L)
__device__ float g_z[(size_t)Bn * 2 * Hn * Ln];   // 256 MB  GEMM output (B,2H,L)
__device__ float g_par[NLn * 4 * Hn * N2n];       // w_re,w_im,cd_re,cd_im
__device__ float g_pool[Bn * Hn];

// ---------------- helpers ----------------
__device__ __forceinline__ float gelu_tanh(float x) {
    float x3 = x * x * x;
    float t = tanhf(0.7978845608028654f * (x + 0.044715f * x3));
    return 0.5f * x * (1.0f + t);
}
__device__ __forceinline__ float sigmoidf_(float x) {
    return 1.0f / (1.0f + expf(-x));
}

// ---------------- 0. precompute discretized SSM params ----------------
__global__ void precompute_kernel(const float* __restrict__ log_dt,
                                  const float* __restrict__ C_re,
                                  const float* __restrict__ C_im,
                                  const float* __restrict__ log_A_real,
                                  const float* __restrict__ A_imag) {
    int idx = blockIdx.x * blockDim.x + threadIdx.x;      // NL*H*N2
    if (idx >= NLn * Hn * N2n) return;
    int i = idx / (Hn * N2n);
    int rem = idx % (Hn * N2n);
    int h = rem / N2n;

    float dt = expf(log_dt[i * Hn + h]);
    float Are = -expf(log_A_real[idx]);
    float Aim = A_imag[idx];
    float dre = Are * dt, dim = Aim * dt;
    float e = expf(dre);
    float w_re = e * cosf(dim);
    float w_im = e * sinf(dim);
    // (w - 1) / A
    float inv = 1.0f / (Are * Are + Aim * Aim);
    float nre = w_re - 1.0f, nim = w_im;
    float fre = (nre * Are + nim * Aim) * inv;
    float fim = (nim * Are - nre * Aim) * inv;
    float cre = C_re[idx], cim = C_im[idx];
    float cd_re = cre * fre - cim * fim;
    float cd_im = cre * fim + cim * fre;

    int base = ((i * 4 + 0) * Hn + h) * N2n + (idx % N2n);
    int stride = Hn * N2n;
    g_par[base + 0 * stride] = w_re;
    g_par[base + 1 * stride] = w_im;
    g_par[base + 2 * stride] = cd_re;
    g_par[base + 3 * stride] = cd_im;
}

// ---------------- 1. encoder: (B,L,1) -> (B,H,L) ----------------
__global__ void encoder_kernel(const float* __restrict__ x,
                               const float* __restrict__ enc_w,
                               const float* __restrict__ enc_b) {
    size_t idx = (size_t)blockIdx.x * blockDim.x + threadIdx.x;
    if (idx >= (size_t)Bn * Hn * Ln) return;
    int l = idx % Ln;
    int h = (idx / Ln) % Hn;
    int b = idx / ((size_t)Hn * Ln);
    g_h[idx] = x[(size_t)b * Ln + l] * enc_w[h] + enc_b[h];
}

// ---------------- 2. SSM scan: warp per (b,h), lane per state ----------------
__global__ void scan_kernel(const float* __restrict__ Dmat, int layer) {
    int warp_g = (blockIdx.x * blockDim.x + threadIdx.x) >> 5;
    int lane = threadIdx.x & 31;
    if (warp_g >= Bn * Hn) return;
    int b = warp_g / Hn, h = warp_g % Hn;

    int pstride = Hn * N2n;
    int pbase = ((layer * 4) * Hn + h) * N2n + lane;
    float w_re = g_par[pbase + 0 * pstride];
    float w_im = g_par[pbase + 1 * pstride];
    float cd_re = g_par[pbase + 2 * pstride];
    float cd_im = g_par[pbase + 3 * pstride];
    float Dh = Dmat[layer * Hn + h];

    const float* u = g_h + (size_t)warp_g * Ln;
    float* y = g_y + (size_t)warp_g * Ln;

    float sre = 0.0f, sim = 0.0f;
    for (int l0 = 0; l0 < Ln; l0 += 32) {
        float uvec = u[l0 + lane];
        float yout = 0.0f;
#pragma unroll
        for (int j = 0; j < 32; ++j) {
            float uj = __shfl_sync(0xffffffffu, uvec, j);
            float nre = fmaf(w_re, sre, fmaf(-w_im, sim, uj));
            float nim = fmaf(w_re, sim, w_im * sre);
            sre = nre; sim = nim;
            float c = fmaf(cd_re, sre, -cd_im * sim);
            c += __shfl_xor_sync(0xffffffffu, c, 16);
            c += __shfl_xor_sync(0xffffffffu, c, 8);
            c += __shfl_xor_sync(0xffffffffu, c, 4);
            c += __shfl_xor_sync(0xffffffffu, c, 2);
            c += __shfl_xor_sync(0xffffffffu, c, 1);
            if (lane == j) yout = c;
        }
        float val = 2.0f * yout + Dh * uvec;
        y[l0 + lane] = gelu_tanh(val);
    }
}

// ---------------- 3. GEMM: Z(b, 512, L) = W(512,256) @ Y(b, 256, L) + bias ----------------
#define BM 128
#define BN 128
#define BK 16
__global__ __launch_bounds__(256) void gemm_kernel(const float* __restrict__ out_w,
                                                   const float* __restrict__ out_b,
                                                   int layer) {
    int b = blockIdx.z;
    const float* Y = g_y + (size_t)b * Hn * Ln;             // (256, L) row-major
    float* Z = g_z + (size_t)b * 2 * Hn * Ln;               // (512, L) row-major
    const float* Wl = out_w + (size_t)layer * 2 * Hn * Hn;  // (512, 256)
    const float* obl = out_b + layer * 2 * Hn;

    int n0 = blockIdx.x * BN;
    int m0 = blockIdx.y * BM;

    __shared__ float As[BK][BM];
    __shared__ float Bs[BK][BN];

    int tid = threadIdx.x;
    int tx = tid & 15, ty = tid >> 4;

    float acc[8][8];
#pragma unroll
    for (int i = 0; i < 8; ++i)
#pragma unroll
        for (int j = 0; j < 8; ++j) acc[i][j] = 0.0f;

    for (int k0 = 0; k0 < Hn; k0 += BK) {
#pragma unroll
        for (int i = 0; i < 8; ++i) {   // 2048 W elems: 128 rows x 16 k
            int idx = tid + i * 256;
            int r = idx >> 4, c = idx & 15;
            As[c][r] = Wl[(size_t)(m0 + r) * Hn + k0 + c];
        }
#pragma unroll
        for (int i = 0; i < 8; ++i) {   // 2048 Y elems: 16 k x 128 n
            int idx = tid + i * 256;
            int r = idx >> 7, c = idx & 127;
            Bs[r][c] = Y[(size_t)(k0 + r) * Ln + n0 + c];
        }
        __syncthreads();
#pragma unroll
        for (int k = 0; k < BK; ++k) {
            float a[8], bb[8];
#pragma unroll
            for (int i = 0; i < 8; ++i) a[i] = As[k][ty * 8 + i];
#pragma unroll
            for (int j = 0; j < 8; ++j) bb[j] = Bs[k][tx * 8 + j];
#pragma unroll
            for (int i = 0; i < 8; ++i)
#pragma unroll
                for (int j = 0; j < 8; ++j)
                    acc[i][j] = fmaf(a[i], bb[j], acc[i][j]);
        }
        __syncthreads();
    }
#pragma unroll
    for (int i = 0; i < 8; ++i) {
        int m = m0 + ty * 8 + i;
        float bias = obl[m];
#pragma unroll
        for (int j = 0; j < 8; ++j) {
            Z[(size_t)m * Ln + n0 + tx * 8 + j] = acc[i][j] + bias;
        }
    }
}

// ---------------- 4. GLU + residual + LayerNorm (in-place on g_h) ----------------
__global__ __launch_bounds__(256) void glu_ln_kernel(const float* __restrict__ ln_w_all,
                                                     const float* __restrict__ ln_b_all,
                                                     int layer) {
    int b = blockIdx.y;
    int l0 = blockIdx.x * 32;
    const float* Z = g_z + (size_t)b * 2 * Hn * Ln;
    float* Hb = g_h + (size_t)b * Hn * Ln;
    const float* lnw = ln_w_all + layer * Hn;
    const float* lnb = ln_b_all + layer * Hn;

    __shared__ float t[Hn][33];
    __shared__ float mu_s[32], rs_s[32];

    int tx = threadIdx.x & 31;   // l within tile (also lane)
    int ty = threadIdx.x >> 5;   // warp id 0..7

    // phase 1: glu + residual -> smem tile [o][l]
    for (int oo = 0; oo < Hn; oo += 8) {
        int o = oo + ty;
        float a = Z[(size_t)o * Ln + l0 + tx];
        float g = Z[(size_t)(o + Hn) * Ln + l0 + tx];
        float hold = Hb[(size_t)o * Ln + l0 + tx];
        t[o][tx] = a * sigmoidf_(g) + hold;
    }
    __syncthreads();

    // phase 2: LN stats per column (each warp handles 4 columns)
    for (int c = ty; c < 32; c += 8) {
        float s = 0.0f, s2 = 0.0f;
#pragma unroll
        for (int k = 0; k < 8; ++k) {
            float v = t[tx + 32 * k][c];
            s += v; s2 += v * v;
        }
#pragma unroll
        for (int off = 16; off > 0; off >>= 1) {
            s += __shfl_xor_sync(0xffffffffu, s, off);
            s2 += __shfl_xor_sync(0xffffffffu, s2, off);
        }
        if (tx == 0) {
            float mu = s * (1.0f / Hn);
            float var = s2 * (1.0f / Hn) - mu * mu;
            mu_s[c] = mu;
            rs_s[c] = rsqrtf(var + 1e-5f);
        }
    }
    __syncthreads();

    // phase 3: normalize + write back (coalesced over l)
    for (int oo = 0; oo < Hn; oo += 8) {
        int o = oo + ty;
        float v = (t[o][tx] - mu_s[tx]) * rs_s[tx] * lnw[o] + lnb[o];
        Hb[(size_t)o * Ln + l0 + tx] = v;
    }
}

// ---------------- 5. mean pool over L ----------------
__global__ void pool_kernel() {
    int row = blockIdx.x;  // b*H+h
    const float* p = g_h + (size_t)row * Ln;
    float s = 0.0f;
    for (int l = threadIdx.x; l < Ln; l += 256) s += p[l];
    __shared__ float red[256];
    red[threadIdx.x] = s;
    __syncthreads();
    for (int off = 128; off > 0; off >>= 1) {
        if (threadIdx.x < off) red[threadIdx.x] += red[threadIdx.x + off];
        __syncthreads();
    }
    if (threadIdx.x == 0) g_pool[row] = red[0] * (1.0f / Ln);
}

// ---------------- 6. decoder ----------------
__global__ void decode_kernel(const float* __restrict__ dec_w,
                              const float* __restrict__ dec_b,
                              float* __restrict__ out) {
    int idx = threadIdx.x;      // 256 = B*DOUT
    int b = idx >> 3, d = idx & 7;
    float s = dec_b[d];
    for (int h = 0; h < Hn; ++h)
        s += g_pool[b * Hn + h] * dec_w[d * Hn + h];
    out[idx] = sigmoidf_(s);
}

// ---------------- launch ----------------
extern "C" void kernel_launch(void* const* d_in, const int* in_sizes, int n_in,
                              void* d_out, int out_size) {
    const float* x          = (const float*)d_in[0];
    const float* enc_w      = (const float*)d_in[1];
    const float* enc_b      = (const float*)d_in[2];
    const float* log_dt     = (const float*)d_in[3];
    const float* C_re       = (const float*)d_in[4];
    const float* C_im       = (const float*)d_in[5];
    const float* log_A_real = (const float*)d_in[6];
    const float* A_imag     = (const float*)d_in[7];
    const float* D          = (const float*)d_in[8];
    const float* out_w      = (const float*)d_in[9];
    const float* out_b      = (const float*)d_in[10];
    const float* ln_w       = (const float*)d_in[11];
    const float* ln_b       = (const float*)d_in[12];
    const float* dec_w      = (const float*)d_in[13];
    const float* dec_b      = (const float*)d_in[14];
    float* out = (float*)d_out;

    precompute_kernel<<<(NLn * Hn * N2n + 255) / 256, 256>>>(log_dt, C_re, C_im,
                                                             log_A_real, A_imag);

    size_t tot = (size_t)Bn * Hn * Ln;
    encoder_kernel<<<(unsigned)((tot + 255) / 256), 256>>>(x, enc_w, enc_b);

    dim3 ggrid(Ln / BN, (2 * Hn) / BM, Bn);
    dim3 egrid(Ln / 32, Bn);

    for (int i = 0; i < NLn; ++i) {
        scan_kernel<<<(Bn * Hn) / 8, 256>>>(D, i);
        gemm_kernel<<<ggrid, 256>>>(out_w, out_b, i);
        glu_ln_kernel<<<egrid, 256>>>(ln_w, ln_b, i);
    }

    pool_kernel<<<Bn * Hn, 256>>>();
    decode_kernel<<<1, 256>>>(dec_w, dec_b, out);
}

// round 3
// speedup vs baseline: 2.2099x; 2.2099x over previous
#include <cuda_runtime.h>
#include <cuda_bf16.h>
#include <math.h>
#include <stdint.h>

// Problem constants
#define Bn   32
#define Ln   4096
#define Hn   256
#define N2n  32
#define NLn  4
#define DOUTn 8

// ---------------- scratch (device globals; no allocation allowed) ----------------
__device__ float g_h[(size_t)Bn * Hn * Ln];       // 128 MB  current hidden (B,H,L)
__device__ float g_y[(size_t)Bn * Hn * Ln];       // 128 MB  gelu(ssm) output (B,H,L)
__device__ float g_z[(size_t)Bn * 2 * Hn * Ln];   // 256 MB  GEMM output (B,2H,L)
__device__ float g_par[NLn * 4 * Hn * N2n];       // w_re,w_im,cd_re,cd_im
__device__ float g_pool[Bn * Hn];

// ---------------- helpers ----------------
__device__ __forceinline__ float gelu_tanh(float x) {
    float x3 = x * x * x;
    float t = tanhf(0.7978845608028654f * (x + 0.044715f * x3));
    return 0.5f * x * (1.0f + t);
}
__device__ __forceinline__ float sigmoidf_(float x) {
    return 1.0f / (1.0f + expf(-x));
}
// tf32 convert: destination must be a b32 register (not .f32) for ptxas
__device__ __forceinline__ uint32_t to_tf32(float x) {
    uint32_t r;
    asm("cvt.rna.tf32.f32 %0, %1;" : "=r"(r) : "f"(x));
    return r;
}

// mma.sync m16n8k8 tf32: D = A@B + D   (A,B as raw b32 tf32 bit patterns)
__device__ __forceinline__ void mma_tf32(float (&d)[4], const uint32_t (&a)[4],
                                         const uint32_t (&b)[2]) {
    asm volatile(
        "mma.sync.aligned.m16n8k8.row.col.f32.tf32.tf32.f32 "
        "{%0,%1,%2,%3}, {%4,%5,%6,%7}, {%8,%9}, {%0,%1,%2,%3};\n"
        : "+f"(d[0]), "+f"(d[1]), "+f"(d[2]), "+f"(d[3])
        : "r"(a[0]), "r"(a[1]), "r"(a[2]), "r"(a[3]), "r"(b[0]), "r"(b[1]));
}

// ---------------- 0. precompute discretized SSM params ----------------
__global__ void precompute_kernel(const float* __restrict__ log_dt,
                                  const float* __restrict__ C_re,
                                  const float* __restrict__ C_im,
                                  const float* __restrict__ log_A_real,
                                  const float* __restrict__ A_imag) {
    int idx = blockIdx.x * blockDim.x + threadIdx.x;      // NL*H*N2
    if (idx >= NLn * Hn * N2n) return;
    int i = idx / (Hn * N2n);
    int rem = idx % (Hn * N2n);
    int h = rem / N2n;

    float dt = expf(log_dt[i * Hn + h]);
    float Are = -expf(log_A_real[idx]);
    float Aim = A_imag[idx];
    float dre = Are * dt, dim = Aim * dt;
    float e = expf(dre);
    float w_re = e * cosf(dim);
    float w_im = e * sinf(dim);
    float inv = 1.0f / (Are * Are + Aim * Aim);
    float nre = w_re - 1.0f, nim = w_im;
    float fre = (nre * Are + nim * Aim) * inv;
    float fim = (nim * Are - nre * Aim) * inv;
    float cre = C_re[idx], cim = C_im[idx];
    float cd_re = cre * fre - cim * fim;
    float cd_im = cre * fim + cim * fre;

    int base = ((i * 4 + 0) * Hn + h) * N2n + (idx % N2n);
    int stride = Hn * N2n;
    g_par[base + 0 * stride] = w_re;
    g_par[base + 1 * stride] = w_im;
    g_par[base + 2 * stride] = 2.0f * cd_re;   // fold the 2x into C
    g_par[base + 3 * stride] = 2.0f * cd_im;
}

// ---------------- 1. encoder: (B,L,1) -> (B,H,L) ----------------
__global__ void encoder_kernel(const float* __restrict__ x,
                               const float* __restrict__ enc_w,
                               const float* __restrict__ enc_b) {
    size_t idx = (size_t)blockIdx.x * blockDim.x + threadIdx.x;
    if (idx >= (size_t)Bn * Hn * Ln) return;
    int l = idx % Ln;
    int h = (idx / Ln) % Hn;
    int b = idx / ((size_t)Hn * Ln);
    g_h[idx] = x[(size_t)b * Ln + l] * enc_w[h] + enc_b[h];
}

// ---------------- 2. SSM scan: warp per (b,h), lane per state ----------------
// smem-based broadcast + transpose-reduce (no shfl butterflies)
__global__ __launch_bounds__(256) void scan_kernel(const float* __restrict__ Dmat,
                                                   int layer) {
    __shared__ float s_c[8][32][36];   // [warp][j][lane], padded to 36
    __shared__ float s_u[8][32];

    int warp = threadIdx.x >> 5;
    int lane = threadIdx.x & 31;
    int warp_g = blockIdx.x * 8 + warp;   // global (b,h) index
    int h = warp_g % Hn;

    int pstride = Hn * N2n;
    int pbase = ((layer * 4) * Hn + h) * N2n + lane;
    float w_re = g_par[pbase + 0 * pstride];
    float w_im = g_par[pbase + 1 * pstride];
    float cd_re = g_par[pbase + 2 * pstride];
    float cd_im = g_par[pbase + 3 * pstride];
    float Dh = Dmat[layer * Hn + h];

    const float* u = g_h + (size_t)warp_g * Ln;
    float* y = g_y + (size_t)warp_g * Ln;

    float sre = 0.0f, sim = 0.0f;
    for (int l0 = 0; l0 < Ln; l0 += 32) {
        float uvec = u[l0 + lane];
        s_u[warp][lane] = uvec;
        __syncwarp();
#pragma unroll
        for (int j = 0; j < 32; ++j) {
            float uj = s_u[warp][j];                       // broadcast LDS
            float nre = fmaf(w_re, sre, fmaf(-w_im, sim, uj));
            float nim = fmaf(w_re, sim, w_im * sre);
            sre = nre; sim = nim;
            s_c[warp][j][lane] = fmaf(cd_re, sre, -cd_im * sim);
        }
        __syncwarp();
        // reduce over states: lane sums its row j=lane
        const float4* row = reinterpret_cast<const float4*>(&s_c[warp][lane][0]);
        float acc = 0.0f;
#pragma unroll
        for (int i = 0; i < 8; ++i) {
            float4 v = row[i];
            acc += (v.x + v.y) + (v.z + v.w);
        }
        __syncwarp();
        float val = acc + Dh * uvec;
        y[l0 + lane] = gelu_tanh(val);
    }
}

// ---------------- 3. tf32 tensor-core GEMM ----------------
// Z(b, 512, L) = W(512,256) @ Y(b, 256, L) + bias
#define GBM 128
#define GBN 128
#define GBK 32
__global__ __launch_bounds__(256) void gemm_tc_kernel(const float* __restrict__ out_w,
                                                      const float* __restrict__ out_b,
                                                      int layer) {
    __shared__ uint32_t As[GBM][36];        // [m][k] pad 36
    __shared__ uint32_t Bs[GBK][GBN + 4];   // [k][n] pad 132

    int b = blockIdx.z;
    const float* Y = g_y + (size_t)b * Hn * Ln;             // (256, L) row-major
    float* Z = g_z + (size_t)b * 2 * Hn * Ln;               // (512, L) row-major
    const float* Wl = out_w + (size_t)layer * 2 * Hn * Hn;  // (512, 256) row-major
    const float* obl = out_b + layer * 2 * Hn;

    int n0 = blockIdx.x * GBN;
    int m0 = blockIdx.y * GBM;

    int tid = threadIdx.x;
    int warp = tid >> 5, lane = tid & 31;
    int wm = warp >> 2;        // 0..1  -> 64 rows
    int wn = warp & 3;         // 0..3  -> 32 cols
    int g = lane >> 2, tig = lane & 3;

    float acc[4][4][4];
#pragma unroll
    for (int mt = 0; mt < 4; ++mt)
#pragma unroll
        for (int nt = 0; nt < 4; ++nt)
#pragma unroll
            for (int r = 0; r < 4; ++r) acc[mt][nt][r] = 0.0f;

    for (int k0 = 0; k0 < Hn; k0 += GBK) {
        // A: 128 rows x 32 k: 1024 float4, 4 per thread
#pragma unroll
        for (int j = 0; j < 4; ++j) {
            int idx = tid + j * 256;
            int r = idx >> 3, c4 = idx & 7;
            float4 v = *reinterpret_cast<const float4*>(&Wl[(size_t)(m0 + r) * Hn + k0 + c4 * 4]);
            uint4 w;
            w.x = to_tf32(v.x); w.y = to_tf32(v.y); w.z = to_tf32(v.z); w.w = to_tf32(v.w);
            *reinterpret_cast<uint4*>(&As[r][c4 * 4]) = w;
        }
        // B: 32 k x 128 n: 1024 float4, 4 per thread
#pragma unroll
        for (int j = 0; j < 4; ++j) {
            int idx = tid + j * 256;
            int r = idx >> 5, c4 = idx & 31;
            float4 v = *reinterpret_cast<const float4*>(&Y[(size_t)(k0 + r) * Ln + n0 + c4 * 4]);
            uint4 w;
            w.x = to_tf32(v.x); w.y = to_tf32(v.y); w.z = to_tf32(v.z); w.w = to_tf32(v.w);
            *reinterpret_cast<uint4*>(&Bs[r][c4 * 4]) = w;
        }
        __syncthreads();

#pragma unroll
        for (int kk = 0; kk < 4; ++kk) {
            int k8 = kk * 8;
            uint32_t afr[4][4];
#pragma unroll
            for (int mt = 0; mt < 4; ++mt) {
                int mrow = wm * 64 + mt * 16;
                afr[mt][0] = As[mrow + g][k8 + tig];
                afr[mt][1] = As[mrow + g + 8][k8 + tig];
                afr[mt][2] = As[mrow + g][k8 + tig + 4];
                afr[mt][3] = As[mrow + g + 8][k8 + tig + 4];
            }
            uint32_t bfr[4][2];
#pragma unroll
            for (int nt = 0; nt < 4; ++nt) {
                int ncol = wn * 32 + nt * 8;
                bfr[nt][0] = Bs[k8 + tig][ncol + g];
                bfr[nt][1] = Bs[k8 + tig + 4][ncol + g];
            }
#pragma unroll
            for (int mt = 0; mt < 4; ++mt)
#pragma unroll
                for (int nt = 0; nt < 4; ++nt)
                    mma_tf32(acc[mt][nt], afr[mt], bfr[nt]);
        }
        __syncthreads();
    }

    // epilogue: + bias, write float2
#pragma unroll
    for (int mt = 0; mt < 4; ++mt) {
        int m = m0 + wm * 64 + mt * 16 + g;
        float bias0 = obl[m];
        float bias1 = obl[m + 8];
#pragma unroll
        for (int nt = 0; nt < 4; ++nt) {
            int n = n0 + wn * 32 + nt * 8 + 2 * tig;
            float2 v0 = make_float2(acc[mt][nt][0] + bias0, acc[mt][nt][1] + bias0);
            float2 v1 = make_float2(acc[mt][nt][2] + bias1, acc[mt][nt][3] + bias1);
            *reinterpret_cast<float2*>(&Z[(size_t)m * Ln + n]) = v0;
            *reinterpret_cast<float2*>(&Z[(size_t)(m + 8) * Ln + n]) = v1;
        }
    }
}

// ---------------- 4. GLU + residual + LayerNorm (in-place on g_h) ----------------
__global__ __launch_bounds__(256) void glu_ln_kernel(const float* __restrict__ ln_w_all,
                                                     const float* __restrict__ ln_b_all,
                                                     int layer) {
    int b = blockIdx.y;
    int l0 = blockIdx.x * 32;
    const float* Z = g_z + (size_t)b * 2 * Hn * Ln;
    float* Hb = g_h + (size_t)b * Hn * Ln;
    const float* lnw = ln_w_all + layer * Hn;
    const float* lnb = ln_b_all + layer * Hn;

    __shared__ float t[Hn][33];
    __shared__ float mu_s[32], rs_s[32];

    int tx = threadIdx.x & 31;
    int ty = threadIdx.x >> 5;

    for (int oo = 0; oo < Hn; oo += 8) {
        int o = oo + ty;
        float a = Z[(size_t)o * Ln + l0 + tx];
        float g = Z[(size_t)(o + Hn) * Ln + l0 + tx];
        float hold = Hb[(size_t)o * Ln + l0 + tx];
        t[o][tx] = a * sigmoidf_(g) + hold;
    }
    __syncthreads();

    for (int c = ty; c < 32; c += 8) {
        float s = 0.0f, s2 = 0.0f;
#pragma unroll
        for (int k = 0; k < 8; ++k) {
            float v = t[tx + 32 * k][c];
            s += v; s2 += v * v;
        }
#pragma unroll
        for (int off = 16; off > 0; off >>= 1) {
            s += __shfl_xor_sync(0xffffffffu, s, off);
            s2 += __shfl_xor_sync(0xffffffffu, s2, off);
        }
        if (tx == 0) {
            float mu = s * (1.0f / Hn);
            float var = s2 * (1.0f / Hn) - mu * mu;
            mu_s[c] = mu;
            rs_s[c] = rsqrtf(var + 1e-5f);
        }
    }
    __syncthreads();

    for (int oo = 0; oo < Hn; oo += 8) {
        int o = oo + ty;
        float v = (t[o][tx] - mu_s[tx]) * rs_s[tx] * lnw[o] + lnb[o];
        Hb[(size_t)o * Ln + l0 + tx] = v;
    }
}

// ---------------- 5. mean pool over L ----------------
__global__ void pool_kernel() {
    int row = blockIdx.x;  // b*H+h
    const float* p = g_h + (size_t)row * Ln;
    float s = 0.0f;
    for (int l = threadIdx.x; l < Ln; l += 256) s += p[l];
    __shared__ float red[256];
    red[threadIdx.x] = s;
    __syncthreads();
    for (int off = 128; off > 0; off >>= 1) {
        if (threadIdx.x < off) red[threadIdx.x] += red[threadIdx.x + off];
        __syncthreads();
    }
    if (threadIdx.x == 0) g_pool[row] = red[0] * (1.0f / Ln);
}

// ---------------- 6. decoder ----------------
__global__ void decode_kernel(const float* __restrict__ dec_w,
                              const float* __restrict__ dec_b,
                              float* __restrict__ out) {
    int idx = threadIdx.x;      // 256 = B*DOUT
    int b = idx >> 3, d = idx & 7;
    float s = dec_b[d];
    for (int h = 0; h < Hn; ++h)
        s += g_pool[b * Hn + h] * dec_w[d * Hn + h];
    out[idx] = sigmoidf_(s);
}

// ---------------- launch ----------------
extern "C" void kernel_launch(void* const* d_in, const int* in_sizes, int n_in,
                              void* d_out, int out_size) {
    const float* x          = (const float*)d_in[0];
    const float* enc_w      = (const float*)d_in[1];
    const float* enc_b      = (const float*)d_in[2];
    const float* log_dt     = (const float*)d_in[3];
    const float* C_re       = (const float*)d_in[4];
    const float* C_im       = (const float*)d_in[5];
    const float* log_A_real = (const float*)d_in[6];
    const float* A_imag     = (const float*)d_in[7];
    const float* D          = (const float*)d_in[8];
    const float* out_w      = (const float*)d_in[9];
    const float* out_b      = (const float*)d_in[10];
    const float* ln_w       = (const float*)d_in[11];
    const float* ln_b       = (const float*)d_in[12];
    const float* dec_w      = (const float*)d_in[13];
    const float* dec_b      = (const float*)d_in[14];
    float* out = (float*)d_out;

    precompute_kernel<<<(NLn * Hn * N2n + 255) / 256, 256>>>(log_dt, C_re, C_im,
                                                             log_A_real, A_imag);

    size_t tot = (size_t)Bn * Hn * Ln;
    encoder_kernel<<<(unsigned)((tot + 255) / 256), 256>>>(x, enc_w, enc_b);

    dim3 ggrid(Ln / GBN, (2 * Hn) / GBM, Bn);
    dim3 egrid(Ln / 32, Bn);

    for (int i = 0; i < NLn; ++i) {
        scan_kernel<<<(Bn * Hn) / 8, 256>>>(D, i);
        gemm_tc_kernel<<<ggrid, 256>>>(out_w, out_b, i);
        glu_ln_kernel<<<egrid, 256>>>(ln_w, ln_b, i);
    }

    pool_kernel<<<Bn * Hn, 256>>>();
    decode_kernel<<<1, 256>>>(dec_w, dec_b, out);
}

// round 6
// speedup vs baseline: 2.5124x; 1.1369x over previous
#include <cuda_runtime.h>
#include <cuda_bf16.h>
#include <math.h>
#include <stdint.h>

// Problem constants
#define Bn   32
#define Ln   4096
#define Hn   256
#define N2n  32
#define NLn  4
#define DOUTn 8

// ---------------- scratch (device globals; no allocation allowed) ----------------
__device__ float    g_h[(size_t)Bn * Hn * Ln];     // 128 MB  current hidden (B,H,L)
__device__ uint32_t g_y[(size_t)Bn * Hn * Ln];     // 128 MB  tf32 bits of gelu(ssm) (B,H,L)
__device__ float    g_z[(size_t)Bn * 2 * Hn * Ln]; // 256 MB  GEMM output (B,2H,L)
__device__ float    g_par[NLn * 4 * Hn * N2n];     // w_re,w_im,cd_re,cd_im
__device__ uint32_t g_wfrag[NLn * 512 * 256];      // W as tf32 bits, MMA-fragment order
__device__ float    g_pool[Bn * Hn];

// ---------------- helpers ----------------
__device__ __forceinline__ float gelu_tanh(float x) {
    float x3 = x * x * x;
    float t = tanhf(0.7978845608028654f * (x + 0.044715f * x3));
    return 0.5f * x * (1.0f + t);
}
__device__ __forceinline__ float sigmoidf_(float x) {
    return 1.0f / (1.0f + expf(-x));
}
__device__ __forceinline__ uint32_t to_tf32(float x) {
    uint32_t r;
    asm("cvt.rna.tf32.f32 %0, %1;" : "=r"(r) : "f"(x));
    return r;
}

// mma.sync m16n8k8 tf32: D = A@B + D   (A,B as raw b32 tf32 bit patterns)
__device__ __forceinline__ void mma_tf32(float (&d)[4], const uint4& a, const uint2& b) {
    asm volatile(
        "mma.sync.aligned.m16n8k8.row.col.f32.tf32.tf32.f32 "
        "{%0,%1,%2,%3}, {%4,%5,%6,%7}, {%8,%9}, {%0,%1,%2,%3};\n"
        : "+f"(d[0]), "+f"(d[1]), "+f"(d[2]), "+f"(d[3])
        : "r"(a.x), "r"(a.y), "r"(a.z), "r"(a.w), "r"(b.x), "r"(b.y));
}

// ---------------- 0a. precompute discretized SSM params ----------------
__global__ void precompute_kernel(const float* __restrict__ log_dt,
                                  const float* __restrict__ C_re,
                                  const float* __restrict__ C_im,
                                  const float* __restrict__ log_A_real,
                                  const float* __restrict__ A_imag) {
    int idx = blockIdx.x * blockDim.x + threadIdx.x;      // NL*H*N2
    if (idx >= NLn * Hn * N2n) return;
    int i = idx / (Hn * N2n);
    int rem = idx % (Hn * N2n);
    int h = rem / N2n;

    float dt = expf(log_dt[i * Hn + h]);
    float Are = -expf(log_A_real[idx]);
    float Aim = A_imag[idx];
    float dre = Are * dt, dim = Aim * dt;
    float e = expf(dre);
    float w_re = e * cosf(dim);
    float w_im = e * sinf(dim);
    float inv = 1.0f / (Are * Are + Aim * Aim);
    float nre = w_re - 1.0f, nim = w_im;
    float fre = (nre * Are + nim * Aim) * inv;
    float fim = (nim * Are - nre * Aim) * inv;
    float cre = C_re[idx], cim = C_im[idx];
    float cd_re = cre * fre - cim * fim;
    float cd_im = cre * fim + cim * fre;

    int base = ((i * 4 + 0) * Hn + h) * N2n + (idx % N2n);
    int stride = Hn * N2n;
    g_par[base + 0 * stride] = w_re;
    g_par[base + 1 * stride] = w_im;
    g_par[base + 2 * stride] = 2.0f * cd_re;   // fold the 2x into C
    g_par[base + 3 * stride] = 2.0f * cd_im;
}

// ---------------- 0b. pre-permute W into tf32 MMA-fragment order ----------------
// per layer: [kc(16)][mt(32)][kk(2)][lane(32)][idx(4)]
__global__ void wfrag_kernel(const float* __restrict__ out_w) {
    int idx = blockIdx.x * blockDim.x + threadIdx.x;    // NL*512*256
    if (idx >= NLn * 512 * 256) return;
    int layer = idx / (512 * 256);
    int rem = idx % (512 * 256);
    int m = rem / 256;
    int k = rem % 256;
    uint32_t val = to_tf32(out_w[idx]);

    int kc = k >> 4;
    int kk = (k >> 3) & 1;
    int tig = k & 3;
    int half = (k >> 2) & 1;
    int mt = m >> 4;
    int g = m & 7;
    int r8 = (m >> 3) & 1;
    int lane = 4 * g + tig;
    int i4 = r8 + 2 * half;
    int dst = (((kc * 32 + mt) * 2 + kk) * 32 + lane) * 4 + i4;
    g_wfrag[layer * 131072 + dst] = val;
}

// ---------------- 1. encoder: (B,L,1) -> (B,H,L) ----------------
__global__ void encoder_kernel(const float* __restrict__ x,
                               const float* __restrict__ enc_w,
                               const float* __restrict__ enc_b) {
    size_t idx = (size_t)blockIdx.x * blockDim.x + threadIdx.x;
    if (idx >= (size_t)Bn * Hn * Ln) return;
    int l = idx % Ln;
    int h = (idx / Ln) % Hn;
    int b = idx / ((size_t)Hn * Ln);
    g_h[idx] = x[(size_t)b * Ln + l] * enc_w[h] + enc_b[h];
}

// ---------------- 2. SSM scan: warp per (b,h), lane per state, 2-step unroll ----------------
__global__ __launch_bounds__(256) void scan_kernel(const float* __restrict__ Dmat,
                                                   int layer) {
    __shared__ float s_c[8][32][36];   // [warp][t][lane]
    __shared__ float s_u[8][32];

    int warp = threadIdx.x >> 5;
    int lane = threadIdx.x & 31;
    int warp_g = blockIdx.x * 8 + warp;   // global (b,h) index
    int h = warp_g % Hn;

    int pstride = Hn * N2n;
    int pbase = ((layer * 4) * Hn + h) * N2n + lane;
    float w_re = g_par[pbase + 0 * pstride];
    float w_im = g_par[pbase + 1 * pstride];
    float cd_re = g_par[pbase + 2 * pstride];
    float cd_im = g_par[pbase + 3 * pstride];
    float Dh = Dmat[layer * Hn + h];

    // 2-step constants
    float w2re = w_re * w_re - w_im * w_im;
    float w2im = 2.0f * w_re * w_im;
    float cwre = cd_re * w_re - cd_im * w_im;
    float cwim = cd_re * w_im + cd_im * w_re;

    const float* u = g_h + (size_t)warp_g * Ln;
    uint32_t* y = g_y + (size_t)warp_g * Ln;

    float sre = 0.0f, sim = 0.0f;
    for (int l0 = 0; l0 < Ln; l0 += 32) {
        float uvec = u[l0 + lane];
        s_u[warp][lane] = uvec;
        __syncwarp();
#pragma unroll
        for (int j = 0; j < 16; ++j) {
            float u1 = s_u[warp][2 * j];
            float u2 = s_u[warp][2 * j + 1];
            float t_re = fmaf(w_re, u1, u2);
            float t_im = w_im * u1;
            float c1 = fmaf(cwre, sre, fmaf(-cwim, sim, cd_re * u1));
            float nre = fmaf(w2re, sre, fmaf(-w2im, sim, t_re));
            float nim = fmaf(w2re, sim, fmaf(w2im, sre, t_im));
            float c2 = fmaf(cd_re, nre, -cd_im * nim);
            s_c[warp][2 * j][lane] = c1;
            s_c[warp][2 * j + 1][lane] = c2;
            sre = nre; sim = nim;
        }
        __syncwarp();
        // reduce over states: lane sums row t=lane
        const float4* row = reinterpret_cast<const float4*>(&s_c[warp][lane][0]);
        float acc = 0.0f;
#pragma unroll
        for (int i = 0; i < 8; ++i) {
            float4 v = row[i];
            acc += (v.x + v.y) + (v.z + v.w);
        }
        __syncwarp();
        float val = acc + Dh * uvec;
        y[l0 + lane] = to_tf32(gelu_tanh(val));
    }
}

// ---------------- 3. tf32 tensor-core GEMM, fragment-ordered A ----------------
// Z(b, 512, L) = W(512,256) @ Y(b, 256, L) + bias
// static smem: As 8K words (32KB) + Bs 16x132 (8.25KB) = ~40KB -> no opt-in needed
__global__ __launch_bounds__(256) void gemm_tc_kernel(const float* __restrict__ out_b,
                                                      int layer) {
    __shared__ uint32_t As[2048 * 4 / 4 * 4];   // 8192 words: [mt(8)][kk(2)][lane(32)][4]
    __shared__ uint32_t Bs[16][132];            // natural [k][n], pad 132

    int b = blockIdx.z;
    const uint32_t* Yb = g_y + (size_t)b * Hn * Ln;         // (256, L) tf32 bits
    float* Z = g_z + (size_t)b * 2 * Hn * Ln;               // (512, L) row-major
    const uint32_t* Wf = g_wfrag + layer * 131072;
    const float* obl = out_b + layer * 2 * Hn;

    int n0 = blockIdx.x * 128;
    int m0 = blockIdx.y * 128;
    int mt0 = m0 >> 4;                                      // global mt base (mult of 8)

    int tid = threadIdx.x;
    int warp = tid >> 5, lane = tid & 31;
    int wm = warp >> 2;        // 0..1  -> 64-row slab
    int wn = warp & 3;         // 0..3  -> 32-col slab
    int g = lane >> 2, tig = lane & 3;

    float acc[4][4][4];
#pragma unroll
    for (int mt = 0; mt < 4; ++mt)
#pragma unroll
        for (int nt = 0; nt < 4; ++nt)
#pragma unroll
            for (int r = 0; r < 4; ++r) acc[mt][nt][r] = 0.0f;

    // register prefetch buffers (kc granularity = k16)
    uint4 pa[2], pb[2];
    {
        const uint4* srcA = reinterpret_cast<const uint4*>(Wf + (0 * 32 + mt0) * 256);
        pa[0] = srcA[tid];
        pa[1] = srcA[tid + 256];
#pragma unroll
        for (int j = 0; j < 2; ++j) {
            int idx4 = tid + j * 256;
            int r = idx4 >> 5, c4 = idx4 & 31;
            pb[j] = *reinterpret_cast<const uint4*>(&Yb[(size_t)r * Ln + n0 + c4 * 4]);
        }
    }

    for (int kc = 0; kc < 16; ++kc) {
        // store staged chunk to smem
        reinterpret_cast<uint4*>(As)[tid] = pa[0];
        reinterpret_cast<uint4*>(As)[tid + 256] = pa[1];
#pragma unroll
        for (int j = 0; j < 2; ++j) {
            int idx4 = tid + j * 256;
            int r = idx4 >> 5, c4 = idx4 & 31;
            *reinterpret_cast<uint4*>(&Bs[r][c4 * 4]) = pb[j];
        }
        __syncthreads();

        // prefetch next chunk
        if (kc + 1 < 16) {
            const uint4* srcA = reinterpret_cast<const uint4*>(Wf + ((kc + 1) * 32 + mt0) * 256);
            pa[0] = srcA[tid];
            pa[1] = srcA[tid + 256];
#pragma unroll
            for (int j = 0; j < 2; ++j) {
                int idx4 = tid + j * 256;
                int r = idx4 >> 5, c4 = idx4 & 31;
                pb[j] = *reinterpret_cast<const uint4*>(
                    &Yb[(size_t)((kc + 1) * 16 + r) * Ln + n0 + c4 * 4]);
            }
        }

        // MMAs: 2 kk sub-chunks of k8
#pragma unroll
        for (int kk = 0; kk < 2; ++kk) {
            int k8 = kk * 8;
            uint4 afr[4];
#pragma unroll
            for (int mt = 0; mt < 4; ++mt)
                afr[mt] = *reinterpret_cast<const uint4*>(
                    &As[(((wm * 4 + mt) * 2 + kk) * 32 + lane) * 4]);
            uint2 bfr[4];
#pragma unroll
            for (int nt = 0; nt < 4; ++nt) {
                int ncol = wn * 32 + nt * 8;
                bfr[nt].x = Bs[k8 + tig][ncol + g];
                bfr[nt].y = Bs[k8 + tig + 4][ncol + g];
            }
#pragma unroll
            for (int mt = 0; mt < 4; ++mt)
#pragma unroll
                for (int nt = 0; nt < 4; ++nt)
                    mma_tf32(acc[mt][nt], afr[mt], bfr[nt]);
        }
        __syncthreads();
    }

    // epilogue: + bias, write float2
#pragma unroll
    for (int mt = 0; mt < 4; ++mt) {
        int m = m0 + wm * 64 + mt * 16 + g;
        float bias0 = obl[m];
        float bias1 = obl[m + 8];
#pragma unroll
        for (int nt = 0; nt < 4; ++nt) {
            int n = n0 + wn * 32 + nt * 8 + 2 * tig;
            float2 v0 = make_float2(acc[mt][nt][0] + bias0, acc[mt][nt][1] + bias0);
            float2 v1 = make_float2(acc[mt][nt][2] + bias1, acc[mt][nt][3] + bias1);
            *reinterpret_cast<float2*>(&Z[(size_t)m * Ln + n]) = v0;
            *reinterpret_cast<float2*>(&Z[(size_t)(m + 8) * Ln + n]) = v1;
        }
    }
}

// ---------------- 4. GLU + residual + LayerNorm (in-place on g_h) ----------------
__global__ __launch_bounds__(256) void glu_ln_kernel(const float* __restrict__ ln_w_all,
                                                     const float* __restrict__ ln_b_all,
                                                     int layer) {
    int b = blockIdx.y;
    int l0 = blockIdx.x * 32;
    const float* Z = g_z + (size_t)b * 2 * Hn * Ln;
    float* Hb = g_h + (size_t)b * Hn * Ln;
    const float* lnw = ln_w_all + layer * Hn;
    const float* lnb = ln_b_all + layer * Hn;

    __shared__ float t[Hn][33];
    __shared__ float mu_s[32], rs_s[32];

    int tx = threadIdx.x & 31;
    int ty = threadIdx.x >> 5;

    for (int oo = 0; oo < Hn; oo += 8) {
        int o = oo + ty;
        float a = Z[(size_t)o * Ln + l0 + tx];
        float g = Z[(size_t)(o + Hn) * Ln + l0 + tx];
        float hold = Hb[(size_t)o * Ln + l0 + tx];
        t[o][tx] = a * sigmoidf_(g) + hold;
    }
    __syncthreads();

    for (int c = ty; c < 32; c += 8) {
        float s = 0.0f, s2 = 0.0f;
#pragma unroll
        for (int k = 0; k < 8; ++k) {
            float v = t[tx + 32 * k][c];
            s += v; s2 += v * v;
        }
#pragma unroll
        for (int off = 16; off > 0; off >>= 1) {
            s += __shfl_xor_sync(0xffffffffu, s, off);
            s2 += __shfl_xor_sync(0xffffffffu, s2, off);
        }
        if (tx == 0) {
            float mu = s * (1.0f / Hn);
            float var = s2 * (1.0f / Hn) - mu * mu;
            mu_s[c] = mu;
            rs_s[c] = rsqrtf(var + 1e-5f);
        }
    }
    __syncthreads();

    for (int oo = 0; oo < Hn; oo += 8) {
        int o = oo + ty;
        float v = (t[o][tx] - mu_s[tx]) * rs_s[tx] * lnw[o] + lnb[o];
        Hb[(size_t)o * Ln + l0 + tx] = v;
    }
}

// ---------------- 5. mean pool over L ----------------
__global__ void pool_kernel() {
    int row = blockIdx.x;  // b*H+h
    const float* p = g_h + (size_t)row * Ln;
    float s = 0.0f;
    for (int l = threadIdx.x; l < Ln; l += 256) s += p[l];
    __shared__ float red[256];
    red[threadIdx.x] = s;
    __syncthreads();
    for (int off = 128; off > 0; off >>= 1) {
        if (threadIdx.x < off) red[threadIdx.x] += red[threadIdx.x + off];
        __syncthreads();
    }
    if (threadIdx.x == 0) g_pool[row] = red[0] * (1.0f / Ln);
}

// ---------------- 6. decoder ----------------
__global__ void decode_kernel(const float* __restrict__ dec_w,
                              const float* __restrict__ dec_b,
                              float* __restrict__ out) {
    int idx = threadIdx.x;      // 256 = B*DOUT
    int b = idx >> 3, d = idx & 7;
    float s = dec_b[d];
    for (int h = 0; h < Hn; ++h)
        s += g_pool[b * Hn + h] * dec_w[d * Hn + h];
    out[idx] = sigmoidf_(s);
}

// ---------------- launch ----------------
extern "C" void kernel_launch(void* const* d_in, const int* in_sizes, int n_in,
                              void* d_out, int out_size) {
    const float* x          = (const float*)d_in[0];
    const float* enc_w      = (const float*)d_in[1];
    const float* enc_b      = (const float*)d_in[2];
    const float* log_dt     = (const float*)d_in[3];
    const float* C_re       = (const float*)d_in[4];
    const float* C_im       = (const float*)d_in[5];
    const float* log_A_real = (const float*)d_in[6];
    const float* A_imag     = (const float*)d_in[7];
    const float* D          = (const float*)d_in[8];
    const float* out_w      = (const float*)d_in[9];
    const float* out_b      = (const float*)d_in[10];
    const float* ln_w       = (const float*)d_in[11];
    const float* ln_b       = (const float*)d_in[12];
    const float* dec_w      = (const float*)d_in[13];
    const float* dec_b      = (const float*)d_in[14];
    float* out = (float*)d_out;

    precompute_kernel<<<(NLn * Hn * N2n + 255) / 256, 256>>>(log_dt, C_re, C_im,
                                                             log_A_real, A_imag);
    wfrag_kernel<<<(NLn * 512 * 256 + 255) / 256, 256>>>(out_w);

    size_t tot = (size_t)Bn * Hn * Ln;
    encoder_kernel<<<(unsigned)((tot + 255) / 256), 256>>>(x, enc_w, enc_b);

    dim3 ggrid(Ln / 128, 512 / 128, Bn);
    dim3 egrid(Ln / 32, Bn);

    for (int i = 0; i < NLn; ++i) {
        scan_kernel<<<(Bn * Hn) / 8, 256>>>(D, i);
        gemm_tc_kernel<<<ggrid, 256>>>(out_b, i);
        glu_ln_kernel<<<egrid, 256>>>(ln_w, ln_b, i);
    }

    pool_kernel<<<Bn * Hn, 256>>>();
    decode_kernel<<<1, 256>>>(dec_w, dec_b, out);
}